// round 6
// baseline (speedup 1.0000x reference)
#include <cuda_runtime.h>
#include <math.h>

#define NN    20
#define INDIM 9
#define HID   128
#define KNN   5
#define STRIDE 132   // 128 + 4 pad; row stride 528B keeps 16B alignment

typedef unsigned long long u64;

// k-quad packed weights: W4[kq][c] = (W[4kq][c], W[4kq+1][c], W[4kq+2][c], W[4kq+3][c])
__device__ __align__(16) float4 g_W4a[32 * HID];
__device__ __align__(16) float4 g_W4b[32 * HID];

__global__ void prep_weights(const float* __restrict__ w1, const float* __restrict__ w2) {
    int t = blockIdx.x * blockDim.x + threadIdx.x;
    if (t < 32 * HID) {
        int kq = t / HID, c = t % HID;
        g_W4a[t] = make_float4(w1[(4 * kq + 0) * HID + c], w1[(4 * kq + 1) * HID + c],
                               w1[(4 * kq + 2) * HID + c], w1[(4 * kq + 3) * HID + c]);
        g_W4b[t] = make_float4(w2[(4 * kq + 0) * HID + c], w2[(4 * kq + 1) * HID + c],
                               w2[(4 * kq + 2) * HID + c], w2[(4 * kq + 3) * HID + c]);
    }
}

__device__ __forceinline__ void ffma2(u64& d, u64 a, u64 b) {
    asm("fma.rn.f32x2 %0, %1, %2, %0;" : "+l"(d) : "l"(a), "l"(b));
}

__device__ __forceinline__ float gelu_exact(float x) {
    return 0.5f * x * (1.0f + erff(x * 0.70710678118654752440f));
}

// C[:,c] = A[20x128] @ W[:,c], f32x2 k-pair accumulators.
// A reads are warp-uniform (broadcast LDS.128); W reads coalesced LDG.128 (L1/L2-hot).
__device__ __forceinline__ void gemm20(const float* __restrict__ A,
                                       const float4* __restrict__ W4,
                                       int c, u64 acc[NN]) {
    #pragma unroll
    for (int r = 0; r < NN; ++r) acc[r] = 0ull;
    #pragma unroll 2
    for (int kq = 0; kq < 32; ++kq) {
        ulonglong2 w = *reinterpret_cast<const ulonglong2*>(&W4[kq * HID + c]);
        #pragma unroll
        for (int r = 0; r < NN; ++r) {
            ulonglong2 a = *reinterpret_cast<const ulonglong2*>(&A[r * STRIDE + 4 * kq]);
            ffma2(acc[r], a.x, w.x);
            ffma2(acc[r], a.y, w.y);
        }
    }
}

// Warp-cooperative LayerNorm stats: warp w handles rows [5w, 5w+5).
__device__ __forceinline__ void ln_stats(const float* __restrict__ buf,
                                         float* __restrict__ st_m,
                                         float* __restrict__ st_r,
                                         int tid) {
    const int w = tid >> 5, lane = tid & 31;
    #pragma unroll
    for (int ii = 0; ii < 5; ++ii) {
        const int i = w * 5 + ii;
        const float* row = buf + i * STRIDE;
        float a0 = row[lane], a1 = row[lane + 32], a2 = row[lane + 64], a3 = row[lane + 96];
        float s = (a0 + a1) + (a2 + a3);
        #pragma unroll
        for (int off = 16; off; off >>= 1) s += __shfl_xor_sync(0xffffffffu, s, off);
        float m = s * (1.0f / 128.0f);
        float q0 = a0 - m, q1 = a1 - m, q2 = a2 - m, q3 = a3 - m;
        float q = q0 * q0 + q1 * q1 + q2 * q2 + q3 * q3;
        #pragma unroll
        for (int off = 16; off; off >>= 1) q += __shfl_xor_sync(0xffffffffu, q, off);
        if (lane == 0) {
            st_m[i] = m;
            st_r[i] = rsqrtf(q * (1.0f / 128.0f) + 1e-5f);
        }
    }
}

__global__ __launch_bounds__(128, 4)
void hbond_gnn_fused(const float* __restrict__ x_all,
                     const float* __restrict__ w_embed,
                     const float* __restrict__ b_embed,
                     const float* __restrict__ b1,
                     const float* __restrict__ b2,
                     const float* __restrict__ g1,
                     const float* __restrict__ be1,
                     const float* __restrict__ g2,
                     const float* __restrict__ be2,
                     float* __restrict__ out) {
    __shared__ float xs[NN * INDIM];
    __shared__ __align__(16) float bufA[NN * STRIDE];
    __shared__ __align__(16) float bufB[NN * STRIDE];
    __shared__ float d2s[NN * NN];
    __shared__ int   nbr[NN * KNN];
    __shared__ float st_m[NN], st_r[NN];

    const int tid = threadIdx.x;      // thread = output column c
    const int c = tid;
    const int b = blockIdx.x;
    const float* x = x_all + (size_t)b * (NN * INDIM);

    // ---- load node features ----
    for (int t = tid; t < NN * INDIM; t += 128) xs[t] = x[t];
    __syncthreads();

    // ---- pairwise squared distances on pos = features [6,9) ----
    for (int t = tid; t < NN * NN; t += 128) {
        const int i = t / NN, j = t % NN;
        float dx = xs[i * INDIM + 6] - xs[j * INDIM + 6];
        float dy = xs[i * INDIM + 7] - xs[j * INDIM + 7];
        float dz = xs[i * INDIM + 8] - xs[j * INDIM + 8];
        d2s[t] = (dx * dx + dy * dy) + dz * dz;
    }
    __syncthreads();

    // ---- top-5 nearest per row; ties -> lower index (matches lax.top_k) ----
    if (tid < NN) {
        const int i = tid;
        unsigned mask = 0;
        for (int r = 0; r < KNN; ++r) {
            float best = 3.4e38f; int bj = 0;
            #pragma unroll
            for (int j = 0; j < NN; ++j) {
                float v = d2s[i * NN + j];
                if (!((mask >> j) & 1u) && v < best) { best = v; bj = j; }
            }
            mask |= 1u << bj;
            nbr[i * KNN + r] = bj;
        }
    }

    // ---- embedding: h0[:,c] -> bufA ----
    {
        float we[INDIM];
        #pragma unroll
        for (int f = 0; f < INDIM; ++f) we[f] = w_embed[f * HID + c];
        const float bev = b_embed[c];
        #pragma unroll
        for (int i = 0; i < NN; ++i) {
            float s = bev;
            #pragma unroll
            for (int f = 0; f < INDIM; ++f) s = fmaf(xs[i * INDIM + f], we[f], s);
            bufA[i * STRIDE + c] = s;
        }
    }
    __syncthreads();      // xs/embed writes + nbr ready

    // ---- agg1: bufB = adj @ bufA ----
    #pragma unroll
    for (int i = 0; i < NN; ++i) {
        float s = 0.0f;
        #pragma unroll
        for (int r = 0; r < KNN; ++r) s += bufA[nbr[i * KNN + r] * STRIDE + c];
        bufB[i * STRIDE + c] = s;
    }
    __syncthreads();

    u64 acc[NN];
    float v[NN], h1[NN];

    // ---- GEMM1: full column c, 20 rows ----
    gemm20(bufB, g_W4a, c, acc);
    {
        const float bias = b1[c];
        #pragma unroll
        for (int r = 0; r < NN; ++r) {
            float2 f = *reinterpret_cast<float2*>(&acc[r]);
            v[r] = f.x + f.y + bias;
        }
    }
    #pragma unroll
    for (int r = 0; r < NN; ++r) bufA[r * STRIDE + c] = v[r];
    __syncthreads();      // also: all GEMM1 reads of bufB complete

    ln_stats(bufA, st_m, st_r, tid);
    __syncthreads();

    // ---- LN1 + GeLU -> h1 (regs) and bufB ----
    {
        const float g = g1[c], e = be1[c];
        #pragma unroll
        for (int r = 0; r < NN; ++r) {
            float hv = gelu_exact(fmaf((v[r] - st_m[r]) * st_r[r], g, e));
            h1[r] = hv;
            bufB[r * STRIDE + c] = hv;
        }
    }
    __syncthreads();

    // ---- agg2 -> bufA ----
    #pragma unroll
    for (int i = 0; i < NN; ++i) {
        float s = 0.0f;
        #pragma unroll
        for (int r = 0; r < KNN; ++r) s += bufB[nbr[i * KNN + r] * STRIDE + c];
        bufA[i * STRIDE + c] = s;
    }
    __syncthreads();

    // ---- GEMM2 ----
    gemm20(bufA, g_W4b, c, acc);
    {
        const float bias = b2[c];
        #pragma unroll
        for (int r = 0; r < NN; ++r) {
            float2 f = *reinterpret_cast<float2*>(&acc[r]);
            v[r] = f.x + f.y + bias;
        }
    }
    #pragma unroll
    for (int r = 0; r < NN; ++r) bufB[r * STRIDE + c] = v[r];
    __syncthreads();      // all GEMM2 reads of bufA complete

    ln_stats(bufB, st_m, st_r, tid);
    __syncthreads();

    // ---- LN2 + residual + GeLU + node-max (all in regs) ----
    {
        const float g = g2[c], e = be2[c];
        float mx = -3.4e38f;
        #pragma unroll
        for (int r = 0; r < NN; ++r) {
            float ln = fmaf((v[r] - st_m[r]) * st_r[r], g, e);
            mx = fmaxf(mx, gelu_exact(h1[r] + ln));
        }
        out[(size_t)b * HID + c] = mx;
    }
}

extern "C" void kernel_launch(void* const* d_in, const int* in_sizes, int n_in,
                              void* d_out, int out_size) {
    const float* x_all   = (const float*)d_in[0];
    const float* w_embed = (const float*)d_in[1];
    const float* b_embed = (const float*)d_in[2];
    const float* w1      = (const float*)d_in[3];
    const float* b1      = (const float*)d_in[4];
    const float* w2      = (const float*)d_in[5];
    const float* b2      = (const float*)d_in[6];
    const float* g1      = (const float*)d_in[7];
    const float* be1     = (const float*)d_in[8];
    const float* g2      = (const float*)d_in[9];
    const float* be2     = (const float*)d_in[10];
    float* out = (float*)d_out;

    const int B = in_sizes[0] / (NN * INDIM);

    prep_weights<<<(32 * HID + 255) / 256, 256>>>(w1, w2);
    hbond_gnn_fused<<<B, 128>>>(x_all, w_embed, b_embed, b1, b2,
                                g1, be1, g2, be2, out);
}

// round 7
// speedup vs baseline: 1.2548x; 1.2548x over previous
#include <cuda_runtime.h>
#include <math.h>

#define NN    20
#define INDIM 9
#define HID   128
#define KNN   5
#define STRIDE 132   // 128 + 4 pad; row stride 528B keeps 16B alignment

typedef unsigned long long u64;

// Lane-swizzled k-pair packed weights.
// For k-pair kp (k = 2kp, 2kp+1), a 1024B block holds 128 float2 (one per column),
// ordered so a warp's ulonglong2 loads are DENSE:
//   idx = kp*128 + half*64 + lane*2 + j   ->   column c = 4*lane + 2*half + j
// Lane `lane` then reads cols (4l,4l+1) at half=0 and (4l+2,4l+3) at half=1,
// each a 16B load with 16B lane stride = 512B dense per warp (4 wavefronts).
__device__ __align__(16) float2 g_Wp1[64 * HID];
__device__ __align__(16) float2 g_Wp2[64 * HID];

__global__ void prep_weights(const float* __restrict__ w1, const float* __restrict__ w2) {
    int t = blockIdx.x * blockDim.x + threadIdx.x;
    if (t < 64 * HID) {
        int kp   = t / 128;
        int rem  = t % 128;
        int half = rem / 64;
        int r2   = rem % 64;
        int lane = r2 / 2;
        int j    = r2 % 2;
        int c    = 4 * lane + 2 * half + j;
        g_Wp1[t] = make_float2(w1[(2 * kp) * HID + c], w1[(2 * kp + 1) * HID + c]);
        g_Wp2[t] = make_float2(w2[(2 * kp) * HID + c], w2[(2 * kp + 1) * HID + c]);
    }
}

__device__ __forceinline__ void ffma2(u64& d, u64 a, u64 b) {
    asm("fma.rn.f32x2 %0, %1, %2, %0;" : "+l"(d) : "l"(a), "l"(b));
}

__device__ __forceinline__ float gelu_exact(float x) {
    return 0.5f * x * (1.0f + erff(x * 0.70710678118654752440f));
}

// C[20x128] = A[20x128] @ W. Thread (rt=tid>>5, ct=tid&31): rows r0..r0+4, cols c0..c0+3.
// A reads warp-uniform (LDS.128 broadcast); W reads dense coalesced LDG.128 (L1-hot).
// acc[i] holds (even-k, odd-k) partial sums; caller adds halves.
__device__ __forceinline__ void gemm20(const float* __restrict__ A,
                                       const float2* __restrict__ Wp,
                                       int r0, int ct, u64 acc[20]) {
    #pragma unroll
    for (int i = 0; i < 20; ++i) acc[i] = 0ull;
    #pragma unroll 2
    for (int kq = 0; kq < 32; ++kq) {          // 4 k's per iter = 2 k-pairs
        u64 a[5][2];
        #pragma unroll
        for (int r = 0; r < 5; ++r) {
            ulonglong2 t = *reinterpret_cast<const ulonglong2*>(&A[(r0 + r) * STRIDE + 4 * kq]);
            a[r][0] = t.x; a[r][1] = t.y;
        }
        #pragma unroll
        for (int kk = 0; kk < 2; ++kk) {
            const float2* wblk = Wp + (2 * kq + kk) * HID;   // 1024B block for this k-pair
            ulonglong2 w01 = *reinterpret_cast<const ulonglong2*>(wblk + ct * 2);        // cols 4ct,4ct+1
            ulonglong2 w23 = *reinterpret_cast<const ulonglong2*>(wblk + 64 + ct * 2);   // cols 4ct+2,4ct+3
            #pragma unroll
            for (int r = 0; r < 5; ++r) {
                ffma2(acc[r * 4 + 0], a[r][kk], w01.x);
                ffma2(acc[r * 4 + 1], a[r][kk], w01.y);
                ffma2(acc[r * 4 + 2], a[r][kk], w23.x);
                ffma2(acc[r * 4 + 3], a[r][kk], w23.y);
            }
        }
    }
}

// LayerNorm stats via warp shuffles: warp owns 5 full rows (lanes cover all 128 cols).
__device__ __forceinline__ void ln_warp(const float v[20], float m[5], float rs[5]) {
    #pragma unroll
    for (int r = 0; r < 5; ++r) {
        float s = (v[r * 4] + v[r * 4 + 1]) + (v[r * 4 + 2] + v[r * 4 + 3]);
        #pragma unroll
        for (int off = 16; off; off >>= 1) s += __shfl_xor_sync(0xffffffffu, s, off);
        float mean = s * (1.0f / 128.0f);
        float q = 0.0f;
        #pragma unroll
        for (int c = 0; c < 4; ++c) { float d = v[r * 4 + c] - mean; q = fmaf(d, d, q); }
        #pragma unroll
        for (int off = 16; off; off >>= 1) q += __shfl_xor_sync(0xffffffffu, q, off);
        m[r]  = mean;
        rs[r] = rsqrtf(q * (1.0f / 128.0f) + 1e-5f);
    }
}

__global__ __launch_bounds__(128, 4)
void hbond_gnn_fused(const float* __restrict__ x_all,
                     const float* __restrict__ w_embed,
                     const float* __restrict__ b_embed,
                     const float* __restrict__ b1,
                     const float* __restrict__ b2,
                     const float* __restrict__ g1,
                     const float* __restrict__ be1,
                     const float* __restrict__ g2,
                     const float* __restrict__ be2,
                     float* __restrict__ out) {
    __shared__ float xs[NN * INDIM];
    __shared__ __align__(16) float bufA[NN * STRIDE];
    __shared__ __align__(16) float bufB[NN * STRIDE];
    __shared__ float d2s[NN * NN];
    __shared__ int   nbr[NN * KNN];
    __shared__ __align__(16) float pmax[4 * HID];

    const int tid = threadIdx.x;
    const int rt = tid >> 5, ct = tid & 31;
    const int r0 = rt * 5, c0 = ct * 4;
    const int b = blockIdx.x;
    const float* x = x_all + (size_t)b * (NN * INDIM);

    // ---- load node features ----
    for (int t = tid; t < NN * INDIM; t += 128) xs[t] = x[t];
    __syncthreads();

    // ---- pairwise squared distances on pos = features [6,9) ----
    for (int t = tid; t < NN * NN; t += 128) {
        const int i = t / NN, j = t % NN;
        float dx = xs[i * INDIM + 6] - xs[j * INDIM + 6];
        float dy = xs[i * INDIM + 7] - xs[j * INDIM + 7];
        float dz = xs[i * INDIM + 8] - xs[j * INDIM + 8];
        d2s[t] = (dx * dx + dy * dy) + dz * dz;
    }
    __syncthreads();

    // ---- top-5 nearest per row; ties -> lower index (matches lax.top_k) ----
    if (tid < NN) {
        const int i = tid;
        unsigned mask = 0;
        for (int r = 0; r < KNN; ++r) {
            float best = 3.4e38f; int bj = 0;
            #pragma unroll
            for (int j = 0; j < NN; ++j) {
                float v = d2s[i * NN + j];
                if (!((mask >> j) & 1u) && v < best) { best = v; bj = j; }
            }
            mask |= 1u << bj;
            nbr[i * KNN + r] = bj;
        }
    }

    // ---- embedding (column layout: thread = column tid) -> bufA ----
    {
        float we[INDIM];
        #pragma unroll
        for (int f = 0; f < INDIM; ++f) we[f] = w_embed[f * HID + tid];
        const float bev = b_embed[tid];
        #pragma unroll
        for (int i = 0; i < NN; ++i) {
            float s = bev;
            #pragma unroll
            for (int f = 0; f < INDIM; ++f) s = fmaf(xs[i * INDIM + f], we[f], s);
            bufA[i * STRIDE + tid] = s;
        }
    }
    __syncthreads();

    // ---- agg1: bufB = adj @ bufA (column layout) ----
    #pragma unroll
    for (int i = 0; i < NN; ++i) {
        float s = 0.0f;
        #pragma unroll
        for (int r = 0; r < KNN; ++r) s += bufA[nbr[i * KNN + r] * STRIDE + tid];
        bufB[i * STRIDE + tid] = s;
    }
    __syncthreads();

    u64 acc[20];
    float v[20], m[5], rs[5];

    // ---- GEMM1: (5 rows x 4 cols)/thread, f32x2 k-pairs, dense W ----
    gemm20(bufB, g_Wp1, r0, ct, acc);
    {
        float4 bb = *reinterpret_cast<const float4*>(&b1[c0]);
        float bias[4] = {bb.x, bb.y, bb.z, bb.w};
        #pragma unroll
        for (int i = 0; i < 20; ++i) {
            float2 f = *reinterpret_cast<float2*>(&acc[i]);
            v[i] = f.x + f.y + bias[i & 3];
        }
    }
    ln_warp(v, m, rs);

    // ---- LN1 + GeLU -> bufB (after all GEMM1 reads complete) ----
    __syncthreads();
    {
        float4 gg = *reinterpret_cast<const float4*>(&g1[c0]);
        float4 ee = *reinterpret_cast<const float4*>(&be1[c0]);
        float g[4] = {gg.x, gg.y, gg.z, gg.w};
        float e[4] = {ee.x, ee.y, ee.z, ee.w};
        #pragma unroll
        for (int r = 0; r < 5; ++r) {
            float4 h;
            float* hp = &h.x;
            #pragma unroll
            for (int c = 0; c < 4; ++c)
                hp[c] = gelu_exact(fmaf((v[r * 4 + c] - m[r]) * rs[r], g[c], e[c]));
            *reinterpret_cast<float4*>(&bufB[(r0 + r) * STRIDE + c0]) = h;
        }
    }
    __syncthreads();

    // ---- agg2: bufA = adj @ bufB ((r,c) layout) ----
    #pragma unroll
    for (int r = 0; r < 5; ++r) {
        const int i = r0 + r;
        float4 s = make_float4(0.f, 0.f, 0.f, 0.f);
        #pragma unroll
        for (int j = 0; j < KNN; ++j) {
            float4 a = *reinterpret_cast<const float4*>(&bufB[nbr[i * KNN + j] * STRIDE + c0]);
            s.x += a.x; s.y += a.y; s.z += a.z; s.w += a.w;
        }
        *reinterpret_cast<float4*>(&bufA[(r0 + r) * STRIDE + c0]) = s;
    }
    __syncthreads();

    // ---- GEMM2 ----
    gemm20(bufA, g_Wp2, r0, ct, acc);
    {
        float4 bb = *reinterpret_cast<const float4*>(&b2[c0]);
        float bias[4] = {bb.x, bb.y, bb.z, bb.w};
        #pragma unroll
        for (int i = 0; i < 20; ++i) {
            float2 f = *reinterpret_cast<float2*>(&acc[i]);
            v[i] = f.x + f.y + bias[i & 3];
        }
    }
    ln_warp(v, m, rs);

    // ---- LN2 + residual (h1 from bufB) + GeLU + per-column partial max ----
    {
        float4 gg = *reinterpret_cast<const float4*>(&g2[c0]);
        float4 ee = *reinterpret_cast<const float4*>(&be2[c0]);
        float g[4] = {gg.x, gg.y, gg.z, gg.w};
        float e[4] = {ee.x, ee.y, ee.z, ee.w};
        float cmax[4] = {-3.4e38f, -3.4e38f, -3.4e38f, -3.4e38f};
        #pragma unroll
        for (int r = 0; r < 5; ++r) {
            float4 h1 = *reinterpret_cast<const float4*>(&bufB[(r0 + r) * STRIDE + c0]);
            const float* h1p = &h1.x;
            #pragma unroll
            for (int c = 0; c < 4; ++c) {
                float ln = fmaf((v[r * 4 + c] - m[r]) * rs[r], g[c], e[c]);
                cmax[c] = fmaxf(cmax[c], gelu_exact(h1p[c] + ln));
            }
        }
        *reinterpret_cast<float4*>(&pmax[rt * HID + c0]) =
            make_float4(cmax[0], cmax[1], cmax[2], cmax[3]);
    }
    __syncthreads();

    // ---- cross-rowgroup max, column tid owns output ----
    {
        float mx = fmaxf(fmaxf(pmax[tid], pmax[HID + tid]),
                         fmaxf(pmax[2 * HID + tid], pmax[3 * HID + tid]));
        out[(size_t)b * HID + tid] = mx;
    }
}

extern "C" void kernel_launch(void* const* d_in, const int* in_sizes, int n_in,
                              void* d_out, int out_size) {
    const float* x_all   = (const float*)d_in[0];
    const float* w_embed = (const float*)d_in[1];
    const float* b_embed = (const float*)d_in[2];
    const float* w1      = (const float*)d_in[3];
    const float* b1      = (const float*)d_in[4];
    const float* w2      = (const float*)d_in[5];
    const float* b2      = (const float*)d_in[6];
    const float* g1      = (const float*)d_in[7];
    const float* be1     = (const float*)d_in[8];
    const float* g2      = (const float*)d_in[9];
    const float* be2     = (const float*)d_in[10];
    float* out = (float*)d_out;

    const int B = in_sizes[0] / (NN * INDIM);

    prep_weights<<<(64 * HID + 255) / 256, 256>>>(w1, w2);
    hbond_gnn_fused<<<B, 128>>>(x_all, w_embed, b_embed, b1, b2,
                                g1, be1, g2, be2, out);
}

// round 8
// speedup vs baseline: 2.3679x; 1.8872x over previous
#include <cuda_runtime.h>
#include <cuda_bf16.h>
#include <math.h>

#define G      4          // graphs per block
#define NODES  80         // G*20
#define NPG    20
#define HID    128
#define INDIM  9
#define KNN    5
#define H1S    132        // fp32 scratch stride (floats)
#define ABS    136        // bf16 activation stride (elements) -> conflict-free

typedef unsigned int u32;

// W fragments in mma order: [matrix][ (mt*8+kt)*32 + lane ]*4 words (4 x bf16x2)
__device__ u32 g_WfHi[2][8192];
__device__ u32 g_WfLo[2][8192];

__global__ void prep_wfrag(const float* __restrict__ w1, const float* __restrict__ w2) {
    int t = blockIdx.x * blockDim.x + threadIdx.x;   // 0..4095
    if (t >= 4096) return;
    int mat = t >> 11, rest = t & 2047;
    int mt = rest >> 8, kt = (rest >> 5) & 7, l = rest & 31;
    int gr = l >> 2, tig = l & 3;
    const float* w = mat ? w2 : w1;
    int base = ((mt * 8 + kt) * 32 + l) * 4;
    #pragma unroll
    for (int r = 0; r < 4; ++r) {
        int row = gr + ((r & 1) ? 8 : 0);             // m within tile
        int kb  = tig * 2 + ((r >= 2) ? 8 : 0);       // k within tile
        int m = mt * 16 + row, k = kt * 16 + kb;
        // A-operand element (m,k) = W^T[m][k] = W[k][m]
        float v0 = w[k * HID + m], v1 = w[(k + 1) * HID + m];
        __nv_bfloat16 h0 = __float2bfloat16(v0), h1 = __float2bfloat16(v1);
        float l0 = v0 - __bfloat162float(h0), l1 = v1 - __bfloat162float(h1);
        __nv_bfloat162 hi; hi.x = h0; hi.y = h1;
        __nv_bfloat162 lo; lo.x = __float2bfloat16(l0); lo.y = __float2bfloat16(l1);
        g_WfHi[mat][base + r] = *(u32*)&hi;
        g_WfLo[mat][base + r] = *(u32*)&lo;
    }
}

__device__ __forceinline__ float gelu_exact(float x) {
    return 0.5f * x * (1.0f + erff(x * 0.70710678118654752440f));
}

#define MMA(d, a, b0v, b1v)                                                       \
    asm volatile("mma.sync.aligned.m16n8k16.row.col.f32.bf16.bf16.f32 "            \
                 "{%0,%1,%2,%3},{%4,%5,%6,%7},{%8,%9},{%0,%1,%2,%3};"              \
                 : "+f"(d[0]), "+f"(d[1]), "+f"(d[2]), "+f"(d[3])                  \
                 : "r"(a[0]), "r"(a[1]), "r"(a[2]), "r"(a[3]), "r"(b0v), "r"(b1v))

// D[feature m][node n] accumulation, 3-term bf16 split.
__device__ __forceinline__ void gemm_mma(const u32* __restrict__ WfHi,
                                         const u32* __restrict__ WfLo,
                                         const __nv_bfloat16* __restrict__ Ahi,
                                         const __nv_bfloat16* __restrict__ Alo,
                                         int mgroup, int ngroup, int lane,
                                         float acc[2][5][4]) {
    const int gr = lane >> 2, tig = lane & 3;
    #pragma unroll
    for (int mt = 0; mt < 2; ++mt)
        #pragma unroll
        for (int nt = 0; nt < 5; ++nt)
            #pragma unroll
            for (int r = 0; r < 4; ++r) acc[mt][nt][r] = 0.0f;

    #pragma unroll
    for (int kt = 0; kt < 8; ++kt) {
        u32 ah[2][4], al[2][4];
        #pragma unroll
        for (int mt = 0; mt < 2; ++mt) {
            int idx = (((mgroup * 2 + mt) * 8 + kt) * 32 + lane) * 4;
            uint4 h = *(const uint4*)&WfHi[idx];
            ah[mt][0] = h.x; ah[mt][1] = h.y; ah[mt][2] = h.z; ah[mt][3] = h.w;
            uint4 lo = *(const uint4*)&WfLo[idx];
            al[mt][0] = lo.x; al[mt][1] = lo.y; al[mt][2] = lo.z; al[mt][3] = lo.w;
        }
        u32 bh[5][2], bl[5][2];
        const int kb = kt * 16 + 2 * tig;
        #pragma unroll
        for (int nt = 0; nt < 5; ++nt) {
            int n0 = ngroup * 40 + nt * 8 + gr;
            bh[nt][0] = *(const u32*)(Ahi + n0 * ABS + kb);
            bh[nt][1] = *(const u32*)(Ahi + n0 * ABS + kb + 8);
            bl[nt][0] = *(const u32*)(Alo + n0 * ABS + kb);
            bl[nt][1] = *(const u32*)(Alo + n0 * ABS + kb + 8);
        }
        #pragma unroll
        for (int mt = 0; mt < 2; ++mt)
            #pragma unroll
            for (int nt = 0; nt < 5; ++nt) {
                MMA(acc[mt][nt], ah[mt], bh[nt][0], bh[nt][1]);
                MMA(acc[mt][nt], ah[mt], bl[nt][0], bl[nt][1]);
                MMA(acc[mt][nt], al[mt], bh[nt][0], bh[nt][1]);
            }
    }
}

// bias + LN (+residual on second) + gelu; writes result fp32 into h1f.
// Contains __syncthreads(): must be called by all 256 threads.
__device__ __forceinline__ void epilogue(float acc[2][5][4],
                                         const float* __restrict__ bias,
                                         const float* __restrict__ gam,
                                         const float* __restrict__ bet,
                                         float* h1f, float* pSum, float* pSq,
                                         float* meanv, float* rstdv,
                                         int mgroup, int ngroup, int lane, int second) {
    const int gr = lane >> 2, tig = lane & 3;
    int   f0[2];
    float bA[2], bB[2], gA[2], gB[2], eA[2], eB[2];
    #pragma unroll
    for (int mt = 0; mt < 2; ++mt) {
        f0[mt] = mgroup * 32 + mt * 16 + gr;
        bA[mt] = bias[f0[mt]];     bB[mt] = bias[f0[mt] + 8];
        gA[mt] = gam[f0[mt]];      gB[mt] = gam[f0[mt] + 8];
        eA[mt] = bet[f0[mt]];      eB[mt] = bet[f0[mt] + 8];
    }
    // ---- stats partials ----
    #pragma unroll
    for (int nt = 0; nt < 5; ++nt) {
        float sA = 0, sB = 0, qA = 0, qB = 0;
        #pragma unroll
        for (int mt = 0; mt < 2; ++mt) {
            float x0 = acc[mt][nt][0] + bA[mt];
            float x1 = acc[mt][nt][1] + bA[mt];
            float x2 = acc[mt][nt][2] + bB[mt];
            float x3 = acc[mt][nt][3] + bB[mt];
            sA += x0 + x2; sB += x1 + x3;
            qA += x0 * x0 + x2 * x2; qB += x1 * x1 + x3 * x3;
        }
        #pragma unroll
        for (int off = 4; off <= 16; off <<= 1) {
            sA += __shfl_xor_sync(0xffffffffu, sA, off);
            sB += __shfl_xor_sync(0xffffffffu, sB, off);
            qA += __shfl_xor_sync(0xffffffffu, qA, off);
            qB += __shfl_xor_sync(0xffffffffu, qB, off);
        }
        if (gr == 0) {
            int nA = ngroup * 40 + nt * 8 + 2 * tig;
            pSum[mgroup * NODES + nA]     = sA;
            pSum[mgroup * NODES + nA + 1] = sB;
            pSq [mgroup * NODES + nA]     = qA;
            pSq [mgroup * NODES + nA + 1] = qB;
        }
    }
    __syncthreads();
    if (threadIdx.x < NODES) {
        int n = threadIdx.x;
        float S = pSum[n] + pSum[NODES + n] + pSum[2 * NODES + n] + pSum[3 * NODES + n];
        float Q = pSq[n]  + pSq[NODES + n]  + pSq[2 * NODES + n]  + pSq[3 * NODES + n];
        float m = S * (1.0f / 128.0f);
        float var = fmaxf(Q * (1.0f / 128.0f) - m * m, 0.0f);
        meanv[n] = m;
        rstdv[n] = rsqrtf(var + 1e-5f);
    }
    __syncthreads();
    // ---- apply ----
    #pragma unroll
    for (int nt = 0; nt < 5; ++nt) {
        int nA = ngroup * 40 + nt * 8 + 2 * tig, nB = nA + 1;
        float mA = meanv[nA], mB = meanv[nB];
        float rA = rstdv[nA], rB = rstdv[nB];
        #pragma unroll
        for (int mt = 0; mt < 2; ++mt) {
            float x0 = acc[mt][nt][0] + bA[mt];
            float x1 = acc[mt][nt][1] + bA[mt];
            float x2 = acc[mt][nt][2] + bB[mt];
            float x3 = acc[mt][nt][3] + bB[mt];
            float v0 = fmaf((x0 - mA) * rA, gA[mt], eA[mt]);
            float v1 = fmaf((x1 - mB) * rB, gA[mt], eA[mt]);
            float v2 = fmaf((x2 - mA) * rA, gB[mt], eB[mt]);
            float v3 = fmaf((x3 - mB) * rB, gB[mt], eB[mt]);
            float* pA0 = h1f + nA * H1S + f0[mt];
            float* pB0 = h1f + nB * H1S + f0[mt];
            if (second) {
                v0 = gelu_exact(pA0[0] + v0);
                v1 = gelu_exact(pB0[0] + v1);
                v2 = gelu_exact(pA0[8] + v2);
                v3 = gelu_exact(pB0[8] + v3);
            } else {
                v0 = gelu_exact(v0); v1 = gelu_exact(v1);
                v2 = gelu_exact(v2); v3 = gelu_exact(v3);
            }
            pA0[0] = v0; pB0[0] = v1; pA0[8] = v2; pB0[8] = v3;
        }
    }
    __syncthreads();
}

// aggregate over knn neighbors from fp32 h1f, split to bf16 hi/lo planes.
__device__ __forceinline__ void agg_split(const float* __restrict__ h1f,
                                          const int* __restrict__ nbr,
                                          __nv_bfloat16* Ahi, __nv_bfloat16* Alo, int t) {
    #pragma unroll
    for (int i = 0; i < 20; ++i) {
        int p = t + 256 * i;              // pair index, 5120 pairs
        int n = p >> 6;
        int fp = (p & 63) * 2;
        const int* nb = &nbr[n * KNN];
        float s0 = 0.0f, s1 = 0.0f;
        #pragma unroll
        for (int r = 0; r < KNN; ++r) {
            const float* row = h1f + nb[r] * H1S + fp;
            s0 += row[0]; s1 += row[1];
        }
        __nv_bfloat16 h0 = __float2bfloat16(s0), h1 = __float2bfloat16(s1);
        __nv_bfloat162 hi; hi.x = h0; hi.y = h1;
        __nv_bfloat162 lo;
        lo.x = __float2bfloat16(s0 - __bfloat162float(h0));
        lo.y = __float2bfloat16(s1 - __bfloat162float(h1));
        *(__nv_bfloat162*)(Ahi + n * ABS + fp) = hi;
        *(__nv_bfloat162*)(Alo + n * ABS + fp) = lo;
    }
}

#define SMEM_BYTES 99840

__global__ __launch_bounds__(256, 2)
void hbond_gnn_mma(const float* __restrict__ x_all,
                   const float* __restrict__ w_embed,
                   const float* __restrict__ b_embed,
                   const float* __restrict__ b1,
                   const float* __restrict__ b2,
                   const float* __restrict__ g1,
                   const float* __restrict__ be1,
                   const float* __restrict__ g2,
                   const float* __restrict__ be2,
                   float* __restrict__ out) {
    extern __shared__ char smem[];
    float* h1f           = (float*)smem;                        // 80*132*4 = 42240
    __nv_bfloat16* Ahi   = (__nv_bfloat16*)(smem + 42240);      // 80*136*2 = 21760
    __nv_bfloat16* Alo   = (__nv_bfloat16*)(smem + 64000);      // 21760
    float* xs            = (float*)(smem + 85760);              // 720*4 = 2880
    float* d2s           = (float*)(smem + 88640);              // 1600*4 = 6400
    int*   nbr           = (int*)(smem + 95040);                // 400*4 = 1600
    float* pSum          = (float*)(smem + 96640);              // 320*4 = 1280
    float* pSq           = (float*)(smem + 97920);              // 1280
    float* meanv         = (float*)(smem + 99200);              // 320
    float* rstdv         = (float*)(smem + 99520);              // 320

    const int t = threadIdx.x;
    const int lane = t & 31, warp = t >> 5;
    const int mgroup = warp >> 1, ngroup = warp & 1;
    const float* x = x_all + (size_t)blockIdx.x * (NODES * INDIM);

    // ---- node features ----
    for (int i = t; i < NODES * INDIM; i += 256) xs[i] = x[i];
    __syncthreads();

    // ---- pairwise d2 per graph ----
    for (int i = t; i < G * NPG * NPG; i += 256) {
        int g = i / 400, rem = i % 400;
        int a = rem / NPG, bb = rem % NPG;
        const float* pa = &xs[(g * NPG + a) * INDIM + 6];
        const float* pb = &xs[(g * NPG + bb) * INDIM + 6];
        float dx = pa[0] - pb[0], dy = pa[1] - pb[1], dz = pa[2] - pb[2];
        d2s[i] = (dx * dx + dy * dy) + dz * dz;
    }
    __syncthreads();

    // ---- top-5 (ties -> lower index) ----
    if (t < NODES) {
        int g = t / NPG, i = t % NPG;
        const float* row = &d2s[g * 400 + i * NPG];
        unsigned mask = 0;
        for (int r = 0; r < KNN; ++r) {
            float best = 3.4e38f; int bj = 0;
            #pragma unroll
            for (int j = 0; j < NPG; ++j) {
                float v = row[j];
                if (!((mask >> j) & 1u) && v < best) { best = v; bj = j; }
            }
            mask |= 1u << bj;
            nbr[t * KNN + r] = g * NPG + bj;
        }
    }

    // ---- embed -> h1f (fp32 scratch) ----
    #pragma unroll
    for (int i = 0; i < 40; ++i) {
        int e = t + 256 * i;             // 10240 elements
        int n = e >> 7, f = e & 127;
        float s = b_embed[f];
        #pragma unroll
        for (int j = 0; j < INDIM; ++j)
            s = fmaf(xs[n * INDIM + j], w_embed[j * HID + f], s);
        h1f[n * H1S + f] = s;
    }
    __syncthreads();   // nbr + embed ready

    // ---- agg1 -> Ahi/Alo ----
    agg_split(h1f, nbr, Ahi, Alo, t);
    __syncthreads();

    float acc[2][5][4];

    // ---- GEMM1 + LN1 + gelu -> h1f ----
    gemm_mma(g_WfHi[0], g_WfLo[0], Ahi, Alo, mgroup, ngroup, lane, acc);
    epilogue(acc, b1, g1, be1, h1f, pSum, pSq, meanv, rstdv, mgroup, ngroup, lane, 0);

    // ---- agg2 -> Ahi/Alo ----
    agg_split(h1f, nbr, Ahi, Alo, t);
    __syncthreads();

    // ---- GEMM2 + LN2 + residual + gelu -> h1f (in place) ----
    gemm_mma(g_WfHi[1], g_WfLo[1], Ahi, Alo, mgroup, ngroup, lane, acc);
    epilogue(acc, b2, g2, be2, h1f, pSum, pSq, meanv, rstdv, mgroup, ngroup, lane, 1);

    // ---- node-max per graph ----
    #pragma unroll
    for (int o = t; o < G * HID; o += 256) {
        int g = o >> 7, f = o & 127;
        float mx = -3.4e38f;
        #pragma unroll
        for (int nn = 0; nn < NPG; ++nn)
            mx = fmaxf(mx, h1f[(g * NPG + nn) * H1S + f]);
        out[((size_t)blockIdx.x * G + g) * HID + f] = mx;
    }
}

extern "C" void kernel_launch(void* const* d_in, const int* in_sizes, int n_in,
                              void* d_out, int out_size) {
    const float* x_all   = (const float*)d_in[0];
    const float* w_embed = (const float*)d_in[1];
    const float* b_embed = (const float*)d_in[2];
    const float* w1      = (const float*)d_in[3];
    const float* b1      = (const float*)d_in[4];
    const float* w2      = (const float*)d_in[5];
    const float* b2      = (const float*)d_in[6];
    const float* g1      = (const float*)d_in[7];
    const float* be1     = (const float*)d_in[8];
    const float* g2      = (const float*)d_in[9];
    const float* be2     = (const float*)d_in[10];
    float* out = (float*)d_out;

    const int B = in_sizes[0] / (NPG * INDIM);

    static int attr_set = 0;
    if (!attr_set) {
        cudaFuncSetAttribute(hbond_gnn_mma,
                             cudaFuncAttributeMaxDynamicSharedMemorySize, SMEM_BYTES);
        attr_set = 1;
    }

    prep_wfrag<<<16, 256>>>(w1, w2);
    hbond_gnn_mma<<<B / G, 256, SMEM_BYTES>>>(x_all, w_embed, b_embed, b1, b2,
                                              g1, be1, g2, be2, out);
}

// round 9
// speedup vs baseline: 2.7241x; 1.1504x over previous
#include <cuda_runtime.h>
#include <cuda_bf16.h>
#include <cuda_fp16.h>
#include <math.h>

#define G      4          // graphs per block
#define NODES  80         // G*20
#define NPG    20
#define HID    128
#define INDIM  9
#define KNN    5
#define H1S    132        // fp32 scratch stride (floats)
#define ABS    136        // fp16 activation stride (elements) -> conflict-free

typedef unsigned int u32;

// W fragments in mma A-operand order, fp16 hi/lo planes:
// [matrix][ (mt8*8+kt)*32 + lane ]*4 words (4 x fp16x2)
__device__ u32 g_WfHi[2][8192];
__device__ u32 g_WfLo[2][8192];

__global__ void prep_wfrag(const float* __restrict__ w1, const float* __restrict__ w2) {
    int t = blockIdx.x * blockDim.x + threadIdx.x;   // 0..4095
    if (t >= 4096) return;
    int mat = t >> 11, rest = t & 2047;
    int mt = rest >> 8, kt = (rest >> 5) & 7, l = rest & 31;
    int gr = l >> 2, tig = l & 3;
    const float* w = mat ? w2 : w1;
    int base = ((mt * 8 + kt) * 32 + l) * 4;
    #pragma unroll
    for (int r = 0; r < 4; ++r) {
        int row = gr + ((r & 1) ? 8 : 0);             // m within tile
        int kb  = tig * 2 + ((r >= 2) ? 8 : 0);       // k within tile
        int m = mt * 16 + row, k = kt * 16 + kb;
        // A-operand element (m,k) = W^T[m][k] = W[k][m]
        float v0 = w[k * HID + m], v1 = w[(k + 1) * HID + m];
        __half h0 = __float2half(v0), h1 = __float2half(v1);
        float l0 = v0 - __half2float(h0), l1 = v1 - __half2float(h1);
        __half2 hi; hi.x = h0; hi.y = h1;
        __half2 lo; lo.x = __float2half(l0); lo.y = __float2half(l1);
        g_WfHi[mat][base + r] = *(u32*)&hi;
        g_WfLo[mat][base + r] = *(u32*)&lo;
    }
}

__device__ __forceinline__ float gelu_exact(float x) {
    return 0.5f * x * (1.0f + erff(x * 0.70710678118654752440f));
}

#define MMA(d, a, b0v, b1v)                                                       \
    asm volatile("mma.sync.aligned.m16n8k16.row.col.f32.f16.f16.f32 "              \
                 "{%0,%1,%2,%3},{%4,%5,%6,%7},{%8,%9},{%0,%1,%2,%3};"              \
                 : "+f"(d[0]), "+f"(d[1]), "+f"(d[2]), "+f"(d[3])                  \
                 : "r"(a[0]), "r"(a[1]), "r"(a[2]), "r"(a[3]), "r"(b0v), "r"(b1v))

// D[feature m][node n]; W = Wh + Wl (fp16 planes), X single fp16 plane.
__device__ __forceinline__ void gemm_mma(const u32* __restrict__ WfHi,
                                         const u32* __restrict__ WfLo,
                                         const __half* __restrict__ Xs,
                                         int mgroup, int ngroup, int lane,
                                         float acc[2][5][4]) {
    const int gr = lane >> 2, tig = lane & 3;
    #pragma unroll
    for (int mt = 0; mt < 2; ++mt)
        #pragma unroll
        for (int nt = 0; nt < 5; ++nt)
            #pragma unroll
            for (int r = 0; r < 4; ++r) acc[mt][nt][r] = 0.0f;

    #pragma unroll
    for (int kt = 0; kt < 8; ++kt) {
        u32 ah[2][4], al[2][4];
        #pragma unroll
        for (int mt = 0; mt < 2; ++mt) {
            int idx = (((mgroup * 2 + mt) * 8 + kt) * 32 + lane) * 4;
            uint4 h = *(const uint4*)&WfHi[idx];
            ah[mt][0] = h.x; ah[mt][1] = h.y; ah[mt][2] = h.z; ah[mt][3] = h.w;
            uint4 lo = *(const uint4*)&WfLo[idx];
            al[mt][0] = lo.x; al[mt][1] = lo.y; al[mt][2] = lo.z; al[mt][3] = lo.w;
        }
        u32 bh[5][2];
        const int kb = kt * 16 + 2 * tig;
        #pragma unroll
        for (int nt = 0; nt < 5; ++nt) {
            int n0 = ngroup * 40 + nt * 8 + gr;
            bh[nt][0] = *(const u32*)(Xs + n0 * ABS + kb);
            bh[nt][1] = *(const u32*)(Xs + n0 * ABS + kb + 8);
        }
        #pragma unroll
        for (int mt = 0; mt < 2; ++mt)
            #pragma unroll
            for (int nt = 0; nt < 5; ++nt) {
                MMA(acc[mt][nt], ah[mt], bh[nt][0], bh[nt][1]);
                MMA(acc[mt][nt], al[mt], bh[nt][0], bh[nt][1]);
            }
    }
}

// bias + LN (+residual on second) + gelu; writes result fp32 into h1f.
// Contains __syncthreads(): must be called by all 256 threads.
__device__ __forceinline__ void epilogue(float acc[2][5][4],
                                         const float* __restrict__ bias,
                                         const float* __restrict__ gam,
                                         const float* __restrict__ bet,
                                         float* h1f, float* pSum, float* pSq,
                                         float* meanv, float* rstdv,
                                         int mgroup, int ngroup, int lane, int second) {
    const int gr = lane >> 2, tig = lane & 3;
    int   f0[2];
    float bA[2], bB[2], gA[2], gB[2], eA[2], eB[2];
    #pragma unroll
    for (int mt = 0; mt < 2; ++mt) {
        f0[mt] = mgroup * 32 + mt * 16 + gr;
        bA[mt] = bias[f0[mt]];     bB[mt] = bias[f0[mt] + 8];
        gA[mt] = gam[f0[mt]];      gB[mt] = gam[f0[mt] + 8];
        eA[mt] = bet[f0[mt]];      eB[mt] = bet[f0[mt] + 8];
    }
    // ---- stats partials ----
    #pragma unroll
    for (int nt = 0; nt < 5; ++nt) {
        float sA = 0, sB = 0, qA = 0, qB = 0;
        #pragma unroll
        for (int mt = 0; mt < 2; ++mt) {
            float x0 = acc[mt][nt][0] + bA[mt];
            float x1 = acc[mt][nt][1] + bA[mt];
            float x2 = acc[mt][nt][2] + bB[mt];
            float x3 = acc[mt][nt][3] + bB[mt];
            sA += x0 + x2; sB += x1 + x3;
            qA += x0 * x0 + x2 * x2; qB += x1 * x1 + x3 * x3;
        }
        #pragma unroll
        for (int off = 4; off <= 16; off <<= 1) {
            sA += __shfl_xor_sync(0xffffffffu, sA, off);
            sB += __shfl_xor_sync(0xffffffffu, sB, off);
            qA += __shfl_xor_sync(0xffffffffu, qA, off);
            qB += __shfl_xor_sync(0xffffffffu, qB, off);
        }
        if (gr == 0) {
            int nA = ngroup * 40 + nt * 8 + 2 * tig;
            pSum[mgroup * NODES + nA]     = sA;
            pSum[mgroup * NODES + nA + 1] = sB;
            pSq [mgroup * NODES + nA]     = qA;
            pSq [mgroup * NODES + nA + 1] = qB;
        }
    }
    __syncthreads();
    if (threadIdx.x < NODES) {
        int n = threadIdx.x;
        float S = pSum[n] + pSum[NODES + n] + pSum[2 * NODES + n] + pSum[3 * NODES + n];
        float Q = pSq[n]  + pSq[NODES + n]  + pSq[2 * NODES + n]  + pSq[3 * NODES + n];
        float m = S * (1.0f / 128.0f);
        float var = fmaxf(Q * (1.0f / 128.0f) - m * m, 0.0f);
        meanv[n] = m;
        rstdv[n] = rsqrtf(var + 1e-5f);
    }
    __syncthreads();
    // ---- apply ----
    #pragma unroll
    for (int nt = 0; nt < 5; ++nt) {
        int nA = ngroup * 40 + nt * 8 + 2 * tig, nB = nA + 1;
        float mA = meanv[nA], mB = meanv[nB];
        float rA = rstdv[nA], rB = rstdv[nB];
        #pragma unroll
        for (int mt = 0; mt < 2; ++mt) {
            float x0 = acc[mt][nt][0] + bA[mt];
            float x1 = acc[mt][nt][1] + bA[mt];
            float x2 = acc[mt][nt][2] + bB[mt];
            float x3 = acc[mt][nt][3] + bB[mt];
            float v0 = fmaf((x0 - mA) * rA, gA[mt], eA[mt]);
            float v1 = fmaf((x1 - mB) * rB, gA[mt], eA[mt]);
            float v2 = fmaf((x2 - mA) * rA, gB[mt], eB[mt]);
            float v3 = fmaf((x3 - mB) * rB, gB[mt], eB[mt]);
            float* pA0 = h1f + nA * H1S + f0[mt];
            float* pB0 = h1f + nB * H1S + f0[mt];
            if (second) {
                v0 = gelu_exact(pA0[0] + v0);
                v1 = gelu_exact(pB0[0] + v1);
                v2 = gelu_exact(pA0[8] + v2);
                v3 = gelu_exact(pB0[8] + v3);
            } else {
                v0 = gelu_exact(v0); v1 = gelu_exact(v1);
                v2 = gelu_exact(v2); v3 = gelu_exact(v3);
            }
            pA0[0] = v0; pB0[0] = v1; pA0[8] = v2; pB0[8] = v3;
        }
    }
    __syncthreads();
}

// aggregate over knn neighbors from fp32 h1f (float4), write single fp16 plane.
__device__ __forceinline__ void agg_split(const float* __restrict__ h1f,
                                          const int* __restrict__ nbr,
                                          __half* __restrict__ Xs, int t) {
    #pragma unroll
    for (int i = 0; i < 10; ++i) {
        int q = t + 256 * i;              // quad index, 2560 quads
        int n = q >> 5;                   // warp-uniform node
        int fq = (q & 31) * 4;
        const int* nb = &nbr[n * KNN];
        float4 s = make_float4(0.f, 0.f, 0.f, 0.f);
        #pragma unroll
        for (int r = 0; r < KNN; ++r) {
            float4 a = *(const float4*)(h1f + nb[r] * H1S + fq);
            s.x += a.x; s.y += a.y; s.z += a.z; s.w += a.w;
        }
        __half2 p0 = __floats2half2_rn(s.x, s.y);
        __half2 p1 = __floats2half2_rn(s.z, s.w);
        uint2 pk; pk.x = *(u32*)&p0; pk.y = *(u32*)&p1;
        *(uint2*)(Xs + n * ABS + fq) = pk;
    }
}

#define SMEM_BYTES 78080

__global__ __launch_bounds__(256, 2)
void hbond_gnn_mma(const float* __restrict__ x_all,
                   const float* __restrict__ w_embed,
                   const float* __restrict__ b_embed,
                   const float* __restrict__ b1,
                   const float* __restrict__ b2,
                   const float* __restrict__ g1,
                   const float* __restrict__ be1,
                   const float* __restrict__ g2,
                   const float* __restrict__ be2,
                   float* __restrict__ out) {
    extern __shared__ char smem[];
    float* h1f   = (float*)smem;                        // 80*132*4 = 42240
    __half* Xs   = (__half*)(smem + 42240);             // 80*136*2 = 21760
    float* xs    = (float*)(smem + 64000);              // 720*4 = 2880
    float* d2s   = (float*)(smem + 66880);              // 1600*4 = 6400
    int*   nbr   = (int*)(smem + 73280);                // 400*4 = 1600
    float* pSum  = (float*)(smem + 74880);              // 320*4 = 1280
    float* pSq   = (float*)(smem + 76160);              // 1280
    float* meanv = (float*)(smem + 77440);              // 320
    float* rstdv = (float*)(smem + 77760);              // 320

    const int t = threadIdx.x;
    const int lane = t & 31, warp = t >> 5;
    const int mgroup = warp >> 1, ngroup = warp & 1;
    const float* x = x_all + (size_t)blockIdx.x * (NODES * INDIM);

    // ---- node features ----
    for (int i = t; i < NODES * INDIM; i += 256) xs[i] = x[i];
    __syncthreads();

    // ---- pairwise d2 per graph ----
    for (int i = t; i < G * NPG * NPG; i += 256) {
        int g = i / 400, rem = i % 400;
        int a = rem / NPG, bb = rem % NPG;
        const float* pa = &xs[(g * NPG + a) * INDIM + 6];
        const float* pb = &xs[(g * NPG + bb) * INDIM + 6];
        float dx = pa[0] - pb[0], dy = pa[1] - pb[1], dz = pa[2] - pb[2];
        d2s[i] = (dx * dx + dy * dy) + dz * dz;
    }
    __syncthreads();

    // ---- top-5 (ties -> lower index) ----
    if (t < NODES) {
        int g = t / NPG, i = t % NPG;
        const float* row = &d2s[g * 400 + i * NPG];
        unsigned mask = 0;
        for (int r = 0; r < KNN; ++r) {
            float best = 3.4e38f; int bj = 0;
            #pragma unroll
            for (int j = 0; j < NPG; ++j) {
                float v = row[j];
                if (!((mask >> j) & 1u) && v < best) { best = v; bj = j; }
            }
            mask |= 1u << bj;
            nbr[t * KNN + r] = g * NPG + bj;
        }
    }

    // ---- embed -> h1f (fp32 scratch) ----
    #pragma unroll
    for (int i = 0; i < 40; ++i) {
        int e = t + 256 * i;             // 10240 elements
        int n = e >> 7, f = e & 127;
        float s = b_embed[f];
        #pragma unroll
        for (int j = 0; j < INDIM; ++j)
            s = fmaf(xs[n * INDIM + j], w_embed[j * HID + f], s);
        h1f[n * H1S + f] = s;
    }
    __syncthreads();   // nbr + embed ready

    // ---- agg1 -> Xs (fp16) ----
    agg_split(h1f, nbr, Xs, t);
    __syncthreads();

    float acc[2][5][4];

    // ---- GEMM1 + LN1 + gelu -> h1f ----
    gemm_mma(g_WfHi[0], g_WfLo[0], Xs, mgroup, ngroup, lane, acc);
    epilogue(acc, b1, g1, be1, h1f, pSum, pSq, meanv, rstdv, mgroup, ngroup, lane, 0);

    // ---- agg2 -> Xs ----
    agg_split(h1f, nbr, Xs, t);
    __syncthreads();

    // ---- GEMM2 + LN2 + residual + gelu -> h1f (in place) ----
    gemm_mma(g_WfHi[1], g_WfLo[1], Xs, mgroup, ngroup, lane, acc);
    epilogue(acc, b2, g2, be2, h1f, pSum, pSq, meanv, rstdv, mgroup, ngroup, lane, 1);

    // ---- node-max per graph ----
    #pragma unroll
    for (int o = t; o < G * HID; o += 256) {
        int g = o >> 7, f = o & 127;
        float mx = -3.4e38f;
        #pragma unroll
        for (int nn = 0; nn < NPG; ++nn)
            mx = fmaxf(mx, h1f[(g * NPG + nn) * H1S + f]);
        out[((size_t)blockIdx.x * G + g) * HID + f] = mx;
    }
}

extern "C" void kernel_launch(void* const* d_in, const int* in_sizes, int n_in,
                              void* d_out, int out_size) {
    const float* x_all   = (const float*)d_in[0];
    const float* w_embed = (const float*)d_in[1];
    const float* b_embed = (const float*)d_in[2];
    const float* w1      = (const float*)d_in[3];
    const float* b1      = (const float*)d_in[4];
    const float* w2      = (const float*)d_in[5];
    const float* b2      = (const float*)d_in[6];
    const float* g1      = (const float*)d_in[7];
    const float* be1     = (const float*)d_in[8];
    const float* g2      = (const float*)d_in[9];
    const float* be2     = (const float*)d_in[10];
    float* out = (float*)d_out;

    const int B = in_sizes[0] / (NPG * INDIM);

    static int attr_set = 0;
    if (!attr_set) {
        cudaFuncSetAttribute(hbond_gnn_mma,
                             cudaFuncAttributeMaxDynamicSharedMemorySize, SMEM_BYTES);
        attr_set = 1;
    }

    prep_wfrag<<<16, 256>>>(w1, w2);
    hbond_gnn_mma<<<B / G, 256, SMEM_BYTES>>>(x_all, w_embed, b_embed, b1, b2,
                                              g1, be1, g2, be2, out);
}

// round 11
// speedup vs baseline: 3.7932x; 1.3925x over previous
#include <cuda_runtime.h>
#include <cuda_bf16.h>
#include <cuda_fp16.h>
#include <math.h>

#define G      4          // graphs per block
#define NODES  80         // G*20
#define NPG    20
#define HID    128
#define INDIM  9
#define KNN    5
#define H1S    132        // fp32 scratch stride (floats)
#define ABS    136        // fp16 activation stride (elements), GEMM2 plane
#define XAS    40         // fp16 xagg stride (halfs): banks (n*20+tig)%32 all distinct

typedef unsigned int u32;

// Fused layer-1 weight: Wfused = We@W1 (9x128), bfused = 5*be@W1 + b1
__device__ float g_Wfused[INDIM * HID];
__device__ float g_bfused[HID];

// mma A-operand fragments, fp16 hi/lo planes.
// Layer-1 (fused, single k-tile): [mt*32+lane]*4 words
__device__ u32 g_Wf1Hi[1024];
__device__ u32 g_Wf1Lo[1024];
// Layer-2 (w2, 8 k-tiles): [(mt*8+kt)*32+lane]*4 words
__device__ u32 g_Wf2Hi[8192];
__device__ u32 g_Wf2Lo[8192];

__global__ void prep_fuse(const float* __restrict__ w_embed,
                          const float* __restrict__ b_embed,
                          const float* __restrict__ w1,
                          const float* __restrict__ b1) {
    int c = blockIdx.x * blockDim.x + threadIdx.x;
    if (c >= HID) return;
    #pragma unroll 1
    for (int j = 0; j < INDIM; ++j) {
        float s = 0.0f;
        for (int k = 0; k < HID; ++k)
            s = fmaf(w_embed[j * HID + k], w1[k * HID + c], s);
        g_Wfused[j * HID + c] = s;
    }
    float sb = 0.0f;
    for (int k = 0; k < HID; ++k)
        sb = fmaf(b_embed[k], w1[k * HID + c], sb);
    g_bfused[c] = 5.0f * sb + b1[c];
}

__global__ void prep_wfrag1() {
    int t = blockIdx.x * blockDim.x + threadIdx.x;   // 0..255
    if (t >= 256) return;
    int mt = t >> 5, l = t & 31;
    int gr = l >> 2, tig = l & 3;
    int base = (mt * 32 + l) * 4;
    #pragma unroll
    for (int r = 0; r < 4; ++r) {
        int row = gr + ((r & 1) ? 8 : 0);
        int kb  = tig * 2 + ((r >= 2) ? 8 : 0);
        int m = mt * 16 + row, k = kb;
        float v0 = (k     < INDIM) ? g_Wfused[k * HID + m]       : 0.0f;
        float v1 = (k + 1 < INDIM) ? g_Wfused[(k + 1) * HID + m] : 0.0f;
        __half h0 = __float2half(v0), h1 = __float2half(v1);
        float l0 = v0 - __half2float(h0), l1 = v1 - __half2float(h1);
        __half2 hi; hi.x = h0; hi.y = h1;
        __half2 lo; lo.x = __float2half(l0); lo.y = __float2half(l1);
        g_Wf1Hi[base + r] = *(u32*)&hi;
        g_Wf1Lo[base + r] = *(u32*)&lo;
    }
}

__global__ void prep_wfrag2(const float* __restrict__ w2) {
    int t = blockIdx.x * blockDim.x + threadIdx.x;   // 0..2047
    if (t >= 2048) return;
    int mt = t >> 8, kt = (t >> 5) & 7, l = t & 31;
    int gr = l >> 2, tig = l & 3;
    int base = ((mt * 8 + kt) * 32 + l) * 4;
    #pragma unroll
    for (int r = 0; r < 4; ++r) {
        int row = gr + ((r & 1) ? 8 : 0);
        int kb  = tig * 2 + ((r >= 2) ? 8 : 0);
        int m = mt * 16 + row, k = kt * 16 + kb;
        float v0 = w2[k * HID + m], v1 = w2[(k + 1) * HID + m];
        __half h0 = __float2half(v0), h1 = __float2half(v1);
        float l0 = v0 - __half2float(h0), l1 = v1 - __half2float(h1);
        __half2 hi; hi.x = h0; hi.y = h1;
        __half2 lo; lo.x = __float2half(l0); lo.y = __float2half(l1);
        g_Wf2Hi[base + r] = *(u32*)&hi;
        g_Wf2Lo[base + r] = *(u32*)&lo;
    }
}

__device__ __forceinline__ float gelu_exact(float x) {
    return 0.5f * x * (1.0f + erff(x * 0.70710678118654752440f));
}

#define MMA(d, a, b0v, b1v)                                                       \
    asm volatile("mma.sync.aligned.m16n8k16.row.col.f32.f16.f16.f32 "              \
                 "{%0,%1,%2,%3},{%4,%5,%6,%7},{%8,%9},{%0,%1,%2,%3};"              \
                 : "+f"(d[0]), "+f"(d[1]), "+f"(d[2]), "+f"(d[3])                  \
                 : "r"(a[0]), "r"(a[1]), "r"(a[2]), "r"(a[3]), "r"(b0v), "r"(b1v))

// Layer-1 fused GEMM: K=16 (9 real), X = xagg hi/lo planes (exact split), 3 mma terms.
__device__ __forceinline__ void gemm1p(const __half* __restrict__ XsHi,
                                       const __half* __restrict__ XsLo,
                                       int mgroup, int ngroup, int lane,
                                       float acc[2][5][4]) {
    const int gr = lane >> 2, tig = lane & 3;
    u32 ah[2][4], al[2][4];
    #pragma unroll
    for (int mt = 0; mt < 2; ++mt) {
        int idx = ((mgroup * 2 + mt) * 32 + lane) * 4;
        uint4 h = *(const uint4*)&g_Wf1Hi[idx];
        ah[mt][0] = h.x; ah[mt][1] = h.y; ah[mt][2] = h.z; ah[mt][3] = h.w;
        uint4 lo = *(const uint4*)&g_Wf1Lo[idx];
        al[mt][0] = lo.x; al[mt][1] = lo.y; al[mt][2] = lo.z; al[mt][3] = lo.w;
    }
    #pragma unroll
    for (int mt = 0; mt < 2; ++mt)
        #pragma unroll
        for (int nt = 0; nt < 5; ++nt)
            #pragma unroll
            for (int r = 0; r < 4; ++r) acc[mt][nt][r] = 0.0f;
    #pragma unroll
    for (int nt = 0; nt < 5; ++nt) {
        int n0 = ngroup * 40 + nt * 8 + gr;
        u32 bh0 = *(const u32*)(XsHi + n0 * XAS + 2 * tig);
        u32 bh1 = *(const u32*)(XsHi + n0 * XAS + 2 * tig + 8);
        u32 bl0 = *(const u32*)(XsLo + n0 * XAS + 2 * tig);
        u32 bl1 = *(const u32*)(XsLo + n0 * XAS + 2 * tig + 8);
        #pragma unroll
        for (int mt = 0; mt < 2; ++mt) {
            MMA(acc[mt][nt], ah[mt], bh0, bh1);
            MMA(acc[mt][nt], al[mt], bh0, bh1);
            MMA(acc[mt][nt], ah[mt], bl0, bl1);
        }
    }
}

// Layer-2 GEMM: W2 = Wh+Wl fp16 planes vs single fp16 activation plane.
__device__ __forceinline__ void gemm2(const __half* __restrict__ Xs,
                                      int mgroup, int ngroup, int lane,
                                      float acc[2][5][4]) {
    const int gr = lane >> 2, tig = lane & 3;
    #pragma unroll
    for (int mt = 0; mt < 2; ++mt)
        #pragma unroll
        for (int nt = 0; nt < 5; ++nt)
            #pragma unroll
            for (int r = 0; r < 4; ++r) acc[mt][nt][r] = 0.0f;
    #pragma unroll
    for (int kt = 0; kt < 8; ++kt) {
        u32 ah[2][4], al[2][4];
        #pragma unroll
        for (int mt = 0; mt < 2; ++mt) {
            int idx = (((mgroup * 2 + mt) * 8 + kt) * 32 + lane) * 4;
            uint4 h = *(const uint4*)&g_Wf2Hi[idx];
            ah[mt][0] = h.x; ah[mt][1] = h.y; ah[mt][2] = h.z; ah[mt][3] = h.w;
            uint4 lo = *(const uint4*)&g_Wf2Lo[idx];
            al[mt][0] = lo.x; al[mt][1] = lo.y; al[mt][2] = lo.z; al[mt][3] = lo.w;
        }
        u32 bh[5][2];
        const int kb = kt * 16 + 2 * tig;
        #pragma unroll
        for (int nt = 0; nt < 5; ++nt) {
            int n0 = ngroup * 40 + nt * 8 + gr;
            bh[nt][0] = *(const u32*)(Xs + n0 * ABS + kb);
            bh[nt][1] = *(const u32*)(Xs + n0 * ABS + kb + 8);
        }
        #pragma unroll
        for (int mt = 0; mt < 2; ++mt)
            #pragma unroll
            for (int nt = 0; nt < 5; ++nt) {
                MMA(acc[mt][nt], ah[mt], bh[nt][0], bh[nt][1]);
                MMA(acc[mt][nt], al[mt], bh[nt][0], bh[nt][1]);
            }
    }
}

// bias + LN (+residual on second) + gelu; writes fp32 into h1f. All 256 threads.
__device__ __forceinline__ void epilogue(float acc[2][5][4],
                                         const float* __restrict__ bias,
                                         const float* __restrict__ gam,
                                         const float* __restrict__ bet,
                                         float* h1f, float* pSum, float* pSq,
                                         float* meanv, float* rstdv,
                                         int mgroup, int ngroup, int lane, int second) {
    const int gr = lane >> 2, tig = lane & 3;
    int   f0[2];
    float bA[2], bB[2], gA[2], gB[2], eA[2], eB[2];
    #pragma unroll
    for (int mt = 0; mt < 2; ++mt) {
        f0[mt] = mgroup * 32 + mt * 16 + gr;
        bA[mt] = bias[f0[mt]];     bB[mt] = bias[f0[mt] + 8];
        gA[mt] = gam[f0[mt]];      gB[mt] = gam[f0[mt] + 8];
        eA[mt] = bet[f0[mt]];      eB[mt] = bet[f0[mt] + 8];
    }
    #pragma unroll
    for (int nt = 0; nt < 5; ++nt) {
        float sA = 0, sB = 0, qA = 0, qB = 0;
        #pragma unroll
        for (int mt = 0; mt < 2; ++mt) {
            float x0 = acc[mt][nt][0] + bA[mt];
            float x1 = acc[mt][nt][1] + bA[mt];
            float x2 = acc[mt][nt][2] + bB[mt];
            float x3 = acc[mt][nt][3] + bB[mt];
            sA += x0 + x2; sB += x1 + x3;
            qA += x0 * x0 + x2 * x2; qB += x1 * x1 + x3 * x3;
        }
        #pragma unroll
        for (int off = 4; off <= 16; off <<= 1) {
            sA += __shfl_xor_sync(0xffffffffu, sA, off);
            sB += __shfl_xor_sync(0xffffffffu, sB, off);
            qA += __shfl_xor_sync(0xffffffffu, qA, off);
            qB += __shfl_xor_sync(0xffffffffu, qB, off);
        }
        if (gr == 0) {
            int nA = ngroup * 40 + nt * 8 + 2 * tig;
            pSum[mgroup * NODES + nA]     = sA;
            pSum[mgroup * NODES + nA + 1] = sB;
            pSq [mgroup * NODES + nA]     = qA;
            pSq [mgroup * NODES + nA + 1] = qB;
        }
    }
    __syncthreads();
    if (threadIdx.x < NODES) {
        int n = threadIdx.x;
        float S = pSum[n] + pSum[NODES + n] + pSum[2 * NODES + n] + pSum[3 * NODES + n];
        float Q = pSq[n]  + pSq[NODES + n]  + pSq[2 * NODES + n]  + pSq[3 * NODES + n];
        float m = S * (1.0f / 128.0f);
        float var = fmaxf(Q * (1.0f / 128.0f) - m * m, 0.0f);
        meanv[n] = m;
        rstdv[n] = rsqrtf(var + 1e-5f);
    }
    __syncthreads();
    #pragma unroll
    for (int nt = 0; nt < 5; ++nt) {
        int nA = ngroup * 40 + nt * 8 + 2 * tig, nB = nA + 1;
        float mA = meanv[nA], mB = meanv[nB];
        float rA = rstdv[nA], rB = rstdv[nB];
        #pragma unroll
        for (int mt = 0; mt < 2; ++mt) {
            float x0 = acc[mt][nt][0] + bA[mt];
            float x1 = acc[mt][nt][1] + bA[mt];
            float x2 = acc[mt][nt][2] + bB[mt];
            float x3 = acc[mt][nt][3] + bB[mt];
            float v0 = fmaf((x0 - mA) * rA, gA[mt], eA[mt]);
            float v1 = fmaf((x1 - mB) * rB, gA[mt], eA[mt]);
            float v2 = fmaf((x2 - mA) * rA, gB[mt], eB[mt]);
            float v3 = fmaf((x3 - mB) * rB, gB[mt], eB[mt]);
            float* pA0 = h1f + nA * H1S + f0[mt];
            float* pB0 = h1f + nB * H1S + f0[mt];
            if (second) {
                v0 = gelu_exact(pA0[0] + v0);
                v1 = gelu_exact(pB0[0] + v1);
                v2 = gelu_exact(pA0[8] + v2);
                v3 = gelu_exact(pB0[8] + v3);
            } else {
                v0 = gelu_exact(v0); v1 = gelu_exact(v1);
                v2 = gelu_exact(v2); v3 = gelu_exact(v3);
            }
            pA0[0] = v0; pB0[0] = v1; pA0[8] = v2; pB0[8] = v3;
        }
    }
    __syncthreads();
}

// aggregate over knn neighbors from fp32 h1f (float4), write single fp16 plane.
__device__ __forceinline__ void agg_split(const float* __restrict__ h1f,
                                          const int* __restrict__ nbr,
                                          __half* __restrict__ Xs, int t) {
    #pragma unroll
    for (int i = 0; i < 10; ++i) {
        int q = t + 256 * i;
        int n = q >> 5;
        int fq = (q & 31) * 4;
        const int* nb = &nbr[n * KNN];
        float4 s = make_float4(0.f, 0.f, 0.f, 0.f);
        #pragma unroll
        for (int r = 0; r < KNN; ++r) {
            float4 a = *(const float4*)(h1f + nb[r] * H1S + fq);
            s.x += a.x; s.y += a.y; s.z += a.z; s.w += a.w;
        }
        __half2 p0 = __floats2half2_rn(s.x, s.y);
        __half2 p1 = __floats2half2_rn(s.z, s.w);
        uint2 pk; pk.x = *(u32*)&p0; pk.y = *(u32*)&p1;
        *(uint2*)(Xs + n * ABS + fq) = pk;
    }
}

#define SMEM_BYTES 78080

__global__ __launch_bounds__(256, 2)
void hbond_gnn_mma(const float* __restrict__ x_all,
                   const float* __restrict__ g1,
                   const float* __restrict__ be1,
                   const float* __restrict__ b2,
                   const float* __restrict__ g2,
                   const float* __restrict__ be2,
                   float* __restrict__ out) {
    extern __shared__ char smem[];
    float* h1f   = (float*)smem;                        // 80*132*4 = 42240
    __half* Xs   = (__half*)(smem + 42240);             // 80*136*2 = 21760 (GEMM2 plane)
    __half* XsHi = (__half*)(smem + 42240);             // aliased: 80*40*2 = 6400
    __half* XsLo = (__half*)(smem + 48640);             // 6400
    float* xs    = (float*)(smem + 64000);              // 720*4 = 2880
    float* d2s   = (float*)(smem + 66880);              // 1600*4 = 6400
    int*   nbr   = (int*)(smem + 73280);                // 400*4 = 1600
    float* pSum  = (float*)(smem + 74880);              // 1280
    float* pSq   = (float*)(smem + 76160);              // 1280
    float* meanv = (float*)(smem + 77440);              // 320
    float* rstdv = (float*)(smem + 77760);              // 320

    const int t = threadIdx.x;
    const int lane = t & 31, warp = t >> 5;
    const int mgroup = warp >> 1, ngroup = warp & 1;
    const float* x = x_all + (size_t)blockIdx.x * (NODES * INDIM);

    // ---- node features ----
    for (int i = t; i < NODES * INDIM; i += 256) xs[i] = x[i];
    __syncthreads();

    // ---- pairwise d2 per graph ----
    for (int i = t; i < G * NPG * NPG; i += 256) {
        int g = i / 400, rem = i % 400;
        int a = rem / NPG, bb = rem % NPG;
        const float* pa = &xs[(g * NPG + a) * INDIM + 6];
        const float* pb = &xs[(g * NPG + bb) * INDIM + 6];
        float dx = pa[0] - pb[0], dy = pa[1] - pb[1], dz = pa[2] - pb[2];
        d2s[i] = (dx * dx + dy * dy) + dz * dz;
    }
    __syncthreads();

    // ---- top-5 (ties -> lower index) + xagg (exact fp32 agg of raw features) ----
    if (t < NODES) {
        int g = t / NPG, i = t % NPG;
        const float* row = &d2s[g * 400 + i * NPG];
        unsigned mask = 0;
        int nb[KNN];
        for (int r = 0; r < KNN; ++r) {
            float best = 3.4e38f; int bj = 0;
            #pragma unroll
            for (int j = 0; j < NPG; ++j) {
                float v = row[j];
                if (!((mask >> j) & 1u) && v < best) { best = v; bj = j; }
            }
            mask |= 1u << bj;
            nb[r] = g * NPG + bj;
            nbr[t * KNN + r] = nb[r];
        }
        __half* hi = XsHi + t * XAS;
        __half* lo = XsLo + t * XAS;
        #pragma unroll
        for (int j = 0; j < INDIM; ++j) {
            float s = 0.0f;
            #pragma unroll
            for (int r = 0; r < KNN; ++r) s += xs[nb[r] * INDIM + j];
            __half h = __float2half(s);
            hi[j] = h;
            lo[j] = __float2half(s - __half2float(h));
        }
        const __half z = __float2half(0.0f);
        #pragma unroll
        for (int j = INDIM; j < 16; ++j) { hi[j] = z; lo[j] = z; }
    }
    __syncthreads();

    float acc[2][5][4];

    // ---- fused layer 1: (adj@x) @ (We@W1) + bfused, then LN1 + gelu -> h1f ----
    gemm1p(XsHi, XsLo, mgroup, ngroup, lane, acc);
    epilogue(acc, g_bfused, g1, be1, h1f, pSum, pSq, meanv, rstdv, mgroup, ngroup, lane, 0);

    // ---- agg2 -> Xs (overwrites XsHi/XsLo region; GEMM1 reads done) ----
    agg_split(h1f, nbr, Xs, t);
    __syncthreads();

    // ---- GEMM2 + LN2 + residual + gelu -> h1f (in place) ----
    gemm2(Xs, mgroup, ngroup, lane, acc);
    epilogue(acc, b2, g2, be2, h1f, pSum, pSq, meanv, rstdv, mgroup, ngroup, lane, 1);

    // ---- node-max per graph ----
    #pragma unroll
    for (int o = t; o < G * HID; o += 256) {
        int g = o >> 7, f = o & 127;
        float mx = -3.4e38f;
        #pragma unroll
        for (int nn = 0; nn < NPG; ++nn)
            mx = fmaxf(mx, h1f[(g * NPG + nn) * H1S + f]);
        out[((size_t)blockIdx.x * G + g) * HID + f] = mx;
    }
}

extern "C" void kernel_launch(void* const* d_in, const int* in_sizes, int n_in,
                              void* d_out, int out_size) {
    const float* x_all   = (const float*)d_in[0];
    const float* w_embed = (const float*)d_in[1];
    const float* b_embed = (const float*)d_in[2];
    const float* w1      = (const float*)d_in[3];
    const float* b1      = (const float*)d_in[4];
    const float* w2      = (const float*)d_in[5];
    const float* b2      = (const float*)d_in[6];
    const float* g1      = (const float*)d_in[7];
    const float* be1     = (const float*)d_in[8];
    const float* g2      = (const float*)d_in[9];
    const float* be2     = (const float*)d_in[10];
    float* out = (float*)d_out;

    const int B = in_sizes[0] / (NPG * INDIM);

    static int attr_set = 0;
    if (!attr_set) {
        cudaFuncSetAttribute(hbond_gnn_mma,
                             cudaFuncAttributeMaxDynamicSharedMemorySize, SMEM_BYTES);
        attr_set = 1;
    }

    prep_fuse<<<1, 128>>>(w_embed, b_embed, w1, b1);
    prep_wfrag1<<<1, 256>>>();
    prep_wfrag2<<<8, 256>>>(w2);
    hbond_gnn_mma<<<B / G, 256, SMEM_BYTES>>>(x_all, g1, be1, b2, g2, be2, out);
}